// round 5
// baseline (speedup 1.0000x reference)
#include <cuda_runtime.h>
#include <cuda_bf16.h>
#include <math.h>
#include <cstdint>

#define Bb   32
#define Kk   64
#define Dd   256
#define LSs  128
#define NLl  2
#define Mm   (Bb*Kk)          // 2048 rows
#define QS   1024             // qkab row stride
#define GK   256              // GEMM K

// ---------------- scratch (no allocs allowed) ----------------
__device__ float g_x   [Mm*Dd];
__device__ float g_qkab[Mm*QS];
__device__ float g_hp  [Mm*Dd];
__device__ float g_bc  [4*Dd];
__device__ float g_s   [Bb*Dd];
// bf16 hi/lo duals
__device__ __nv_bfloat16 g_xh [Mm*Dd], g_xl [Mm*Dd];
__device__ __nv_bfloat16 g_ggh[Mm*Dd], g_ggl[Mm*Dd];
__device__ __nv_bfloat16 g_hh [Mm*Dd], g_hl [Mm*Dd];
__device__ __nv_bfloat16 g_th [Mm*Dd], g_tl [Mm*Dd];
__device__ __nv_bfloat16 g_wch[4*Dd*Dd], g_wcl[4*Dd*Dd];
__device__ __nv_bfloat16 g_w2h[3*Dd*Dd], g_w2l[3*Dd*Dd];

// ---------------- fast exact-enough gelu (A&S 7.1.26, |err| < 2e-7) ----------------
__device__ __forceinline__ float gelu_fast(float x) {
    float z = fabsf(x) * 0.7071067811865476f;
    float w = fmaf(z, 0.3275911f, 1.0f);
    float t;
    asm("rcp.approx.f32 %0, %1;" : "=f"(t) : "f"(w));
    float ez = __expf(-z * z);
    float p = fmaf(fmaf(fmaf(fmaf(1.061405429f, t, -1.453152027f), t,
                     1.421413741f), t, -0.284496736f), t, 0.254829592f) * t;
    float e = fmaf(-p, ez, 1.0f);                 // erf(|z|)
    float phi = fmaf(copysignf(e, x), 0.5f, 0.5f);
    return x * phi;
}

__device__ __forceinline__ uint32_t smem_u32(const void* p) {
    uint32_t a;
    asm("{ .reg .u64 t; cvta.to.shared.u64 t, %1; cvt.u32.u64 %0, t; }" : "=r"(a) : "l"(p));
    return a;
}

// split fp32 -> (hi, lo) bf16
__device__ __forceinline__ void split_bf16(float v, __nv_bfloat16& h, __nv_bfloat16& l) {
    h = __float2bfloat16(v);
    l = __float2bfloat16(v - __bfloat162float(h));
}
// pack pair (x0, x1) -> bf16x2 words for hi and lo
__device__ __forceinline__ void split_pair(float x0, float x1, uint32_t& hp, uint32_t& lp) {
    asm("cvt.rn.bf16x2.f32 %0, %1, %2;" : "=r"(hp) : "f"(x1), "f"(x0));
    float h0 = __uint_as_float(hp << 16);
    float h1 = __uint_as_float(hp & 0xffff0000u);
    asm("cvt.rn.bf16x2.f32 %0, %1, %2;" : "=r"(lp) : "f"(x1 - h1), "f"(x0 - h0));
}

// ---------------- warp MMA primitives ----------------
__device__ __forceinline__ void ldsm_x4(uint32_t* r, uint32_t addr) {
    asm volatile("ldmatrix.sync.aligned.m8n8.x4.shared.b16 {%0,%1,%2,%3}, [%4];"
        : "=r"(r[0]), "=r"(r[1]), "=r"(r[2]), "=r"(r[3]) : "r"(addr));
}
__device__ __forceinline__ void ldsm_x2(uint32_t* r, uint32_t addr) {
    asm volatile("ldmatrix.sync.aligned.m8n8.x2.shared.b16 {%0,%1}, [%2];"
        : "=r"(r[0]), "=r"(r[1]) : "r"(addr));
}
__device__ __forceinline__ void mma_bf16(float* c, const uint32_t* a, const uint32_t* b) {
    asm volatile("mma.sync.aligned.m16n8k16.row.col.f32.bf16.bf16.f32 "
        "{%0,%1,%2,%3}, {%4,%5,%6,%7}, {%8,%9}, {%0,%1,%2,%3};"
        : "+f"(c[0]), "+f"(c[1]), "+f"(c[2]), "+f"(c[3])
        : "r"(a[0]), "r"(a[1]), "r"(a[2]), "r"(a[3]), "r"(b[0]), "r"(b[1]));
}

// ---------------- smem layout for tc_gemm ----------------
#define LDSB  528
#define SM_AH 0
#define SM_AL (SM_AH + 128*LDSB)
#define SM_BH (SM_AL + 128*LDSB)
#define SM_BL (SM_BH + 64*LDSB)
#define SM_TOT (SM_BL + 64*LDSB)     // 202752 B

// stage pre-converted bf16 duals: pure uint4 copies
template<int ROWS>
__device__ __forceinline__ void stage_dual(const __nv_bfloat16* __restrict__ Gh,
                                           const __nv_bfloat16* __restrict__ Gl,
                                           char* smh, char* sml, int tid) {
    const int ngroups = ROWS * (GK / 8);
    for (int g = tid; g < ngroups; g += 256) {
        int row = g >> 5;
        int k0  = (g & 31) * 8;
        uint4 vh = *(const uint4*)(Gh + (size_t)row * GK + k0);
        uint4 vl = *(const uint4*)(Gl + (size_t)row * GK + k0);
        uint32_t off = (uint32_t)(row * LDSB + k0 * 2);
        *(uint4*)(smh + off) = vh;
        *(uint4*)(sml + off) = vl;
    }
}

// ---------------- bf16x3 GEMM: C = A[M,256] @ Bw[N,256]^T (+bias)(+gelu)(+resid) ----
// CTA: 128x64 tile, 8 warps (4M x 2N), warp tile 32x32.
// Cf (fp32, stride ldc) optional; Ch/Cl (bf16 duals, stride 256) optional.
__global__ void __launch_bounds__(256)
tc_gemm(const __nv_bfloat16* __restrict__ Ah, const __nv_bfloat16* __restrict__ Al,
        const __nv_bfloat16* __restrict__ Bh, const __nv_bfloat16* __restrict__ Bl,
        const float* __restrict__ bias, const float* __restrict__ resid,
        float* __restrict__ Cf, int ldc,
        __nv_bfloat16* __restrict__ Ch, __nv_bfloat16* __restrict__ Cl,
        int do_gelu)
{
    extern __shared__ char sm[];
    uint32_t smb = smem_u32(sm);
    const int tid = threadIdx.x, lane = tid & 31, wid = tid >> 5;
    const int warp_m = wid & 3, warp_n = wid >> 2;
    const int bm = blockIdx.y * 128, bn = blockIdx.x * 64;

    stage_dual<128>(Ah + (size_t)bm * GK, Al + (size_t)bm * GK, sm + SM_AH, sm + SM_AL, tid);
    stage_dual<64>( Bh + (size_t)bn * GK, Bl + (size_t)bn * GK, sm + SM_BH, sm + SM_BL, tid);
    __syncthreads();

    float acc[2][4][4];
    #pragma unroll
    for (int i = 0; i < 2; i++)
        #pragma unroll
        for (int j = 0; j < 4; j++)
            #pragma unroll
            for (int e = 0; e < 4; e++) acc[i][j][e] = 0.f;

    uint32_t a_base[2], b_base[4];
    #pragma unroll
    for (int tm = 0; tm < 2; tm++)
        a_base[tm] = smb + SM_AH
                   + (uint32_t)((warp_m * 32 + tm * 16 + (lane & 15)) * LDSB)
                   + (uint32_t)((lane >> 4) * 16);
    #pragma unroll
    for (int tn = 0; tn < 4; tn++)
        b_base[tn] = smb + SM_BH
                   + (uint32_t)((warp_n * 32 + tn * 8 + (lane & 7)) * LDSB)
                   + (uint32_t)(((lane >> 3) & 1) * 16);

    const uint32_t DA = SM_AL - SM_AH;
    const uint32_t DB = SM_BL - SM_BH;

    #pragma unroll
    for (int ks = 0; ks < 16; ks++) {
        const uint32_t kb = ks * 32;
        uint32_t ah[2][4], al[2][4], bh[4][2], bl[4][2];
        #pragma unroll
        for (int tm = 0; tm < 2; tm++) {
            ldsm_x4(ah[tm], a_base[tm] + kb);
            ldsm_x4(al[tm], a_base[tm] + kb + DA);
        }
        #pragma unroll
        for (int tn = 0; tn < 4; tn++) {
            ldsm_x2(bh[tn], b_base[tn] + kb);
            ldsm_x2(bl[tn], b_base[tn] + kb + DB);
        }
        #pragma unroll
        for (int tm = 0; tm < 2; tm++)
            #pragma unroll
            for (int tn = 0; tn < 4; tn++) {
                mma_bf16(acc[tm][tn], ah[tm], bh[tn]);
                mma_bf16(acc[tm][tn], ah[tm], bl[tn]);
                mma_bf16(acc[tm][tn], al[tm], bh[tn]);
            }
    }

    #pragma unroll
    for (int tm = 0; tm < 2; tm++) {
        int r0 = bm + warp_m * 32 + tm * 16 + (lane >> 2);
        #pragma unroll
        for (int tn = 0; tn < 4; tn++) {
            int c = bn + warp_n * 32 + tn * 8 + (lane & 3) * 2;
            #pragma unroll
            for (int h = 0; h < 2; h++) {
                int r = r0 + h * 8;
                float x0 = acc[tm][tn][h * 2 + 0];
                float x1 = acc[tm][tn][h * 2 + 1];
                if (bias)  { x0 += bias[c]; x1 += bias[c + 1]; }
                if (do_gelu) { x0 = gelu_fast(x0); x1 = gelu_fast(x1); }
                if (resid) {
                    float2 rr = *(const float2*)(resid + (size_t)r * ldc + c);
                    x0 += rr.x; x1 += rr.y;
                }
                if (Cf) *(float2*)(Cf + (size_t)r * ldc + c) = make_float2(x0, x1);
                if (Ch) {
                    uint32_t hp, lp;
                    split_pair(x0, x1, hp, lp);
                    *(uint32_t*)(Ch + (size_t)r * Dd + c) = hp;
                    *(uint32_t*)(Cl + (size_t)r * Dd + c) = lp;
                }
            }
        }
    }
}

// ---------------- producer/conversion kernels ----------------
__global__ void copy_conv_kernel(const float* __restrict__ src, float* __restrict__ dst,
                                 __nv_bfloat16* __restrict__ dh, __nv_bfloat16* __restrict__ dl,
                                 int n) {
    int i = blockIdx.x * blockDim.x + threadIdx.x;
    if (i < n) {
        float v = src[i];
        dst[i] = v;
        __nv_bfloat16 h, l; split_bf16(v, h, l);
        dh[i] = h; dl[i] = l;
    }
}

// pack combined weights (duals): rows [0:256)=k_w, [256:512)=q_w, [512:768)=W1a+W1b, [768:1024)=W1b
__global__ void pack_kernel(const float* __restrict__ kw, const float* __restrict__ qw,
                            const float* __restrict__ w1, const float* __restrict__ rb1,
                            __nv_bfloat16* __restrict__ wch, __nv_bfloat16* __restrict__ wcl,
                            float* __restrict__ bc) {
    int i = blockIdx.x * blockDim.x + threadIdx.x;
    int r = i >> 8, c = i & 255;
    float v;
    if (r < 256)      v = kw[r * Dd + c];
    else if (r < 512) v = qw[(r - 256) * Dd + c];
    else if (r < 768) { int d = r - 512; v = w1[d * 2 * Dd + c] + w1[d * 2 * Dd + Dd + c]; }
    else              { int d = r - 768; v = w1[d * 2 * Dd + Dd + c]; }
    __nv_bfloat16 h, l; split_bf16(v, h, l);
    wch[i] = h; wcl[i] = l;
    if (i < 4 * Dd) bc[i] = (i >= 512 && i < 768) ? rb1[i - 512] : 0.f;
}

// pack rw2|mw1|mw2 as dual slabs
__global__ void w2pack_kernel(const float* __restrict__ rw2, const float* __restrict__ mw1,
                              const float* __restrict__ mw2,
                              __nv_bfloat16* __restrict__ w2h, __nv_bfloat16* __restrict__ w2l) {
    int i = blockIdx.x * blockDim.x + threadIdx.x;   // [0, 3*65536)
    int s = i >> 16, o = i & 65535;
    const float* src = (s == 0) ? rw2 : ((s == 1) ? mw1 : mw2);
    float v = src[o];
    __nv_bfloat16 h, l; split_bf16(v, h, l);
    w2h[i] = h; w2l[i] = l;
}

// ---------------- attention + gelu aggregation, 4 queries per block ----------------
// qkab row layout: [k(256) | q(256) | a(256) | bb(256)]
__global__ void __launch_bounds__(256)
attn_kernel(const float* __restrict__ qkab,
            __nv_bfloat16* __restrict__ ggh, __nv_bfloat16* __restrict__ ggl)
{
    const int b = blockIdx.y, i0 = blockIdx.x * 4;
    const int tid = threadIdx.x;
    const int lane = tid & 31, warp = tid >> 5;

    __shared__ float sq[4][Dd];
    __shared__ float sa[4][Dd];
    __shared__ float sl[4][Kk];
    __shared__ float sp[4][Kk];

    const float* base = qkab + (size_t)b * Kk * QS;

    #pragma unroll
    for (int ii = 0; ii < 4; ii++) {
        const float* row = base + (size_t)(i0 + ii) * QS;
        sq[ii][tid] = row[256 + tid];
        sa[ii][tid] = row[512 + tid];
    }
    __syncthreads();

    // logits: warp handles j, computes dots for all 4 queries (k loaded once)
    for (int j = warp; j < Kk; j += 8) {
        const float* kj = base + (size_t)j * QS;
        float kv[8];
        #pragma unroll
        for (int m = 0; m < 8; m++) kv[m] = kj[lane + 32 * m];
        #pragma unroll
        for (int ii = 0; ii < 4; ii++) {
            float t = 0.f;
            #pragma unroll
            for (int m = 0; m < 8; m++) t = fmaf(sq[ii][lane + 32 * m], kv[m], t);
            #pragma unroll
            for (int o = 16; o; o >>= 1) t += __shfl_xor_sync(0xffffffffu, t, o);
            if (lane == 0) sl[ii][j] = t * 0.0625f;   // D^-0.5
        }
    }
    __syncthreads();

    // 4 softmaxes: warp w < 4 handles query w
    if (warp < 4) {
        float v0 = sl[warp][lane], v1 = sl[warp][lane + 32];
        float m = fmaxf(v0, v1);
        #pragma unroll
        for (int o = 16; o; o >>= 1) m = fmaxf(m, __shfl_xor_sync(0xffffffffu, m, o));
        float e0 = __expf(v0 - m), e1 = __expf(v1 - m);
        float s = e0 + e1;
        #pragma unroll
        for (int o = 16; o; o >>= 1) s += __shfl_xor_sync(0xffffffffu, s, o);
        float inv = 1.f / s;
        sp[warp][lane] = e0 * inv; sp[warp][lane + 32] = e1 * inv;
    }
    __syncthreads();

    // aggregation: thread owns dim d = tid; bb loaded once, 4 gelu per j
    const float a0 = sa[0][tid], a1 = sa[1][tid], a2 = sa[2][tid], a3 = sa[3][tid];
    float c0 = 0.f, c1 = 0.f, c2 = 0.f, c3 = 0.f;
    const float* bbp = base + 768 + tid;
    #pragma unroll 4
    for (int j = 0; j < Kk; j++) {
        float bb = __ldg(bbp + (size_t)j * QS);
        c0 = fmaf(sp[0][j], gelu_fast(a0 - bb), c0);
        c1 = fmaf(sp[1][j], gelu_fast(a1 - bb), c1);
        c2 = fmaf(sp[2][j], gelu_fast(a2 - bb), c2);
        c3 = fmaf(sp[3][j], gelu_fast(a3 - bb), c3);
    }
    float cc[4] = {c0, c1, c2, c3};
    #pragma unroll
    for (int ii = 0; ii < 4; ii++) {
        size_t idx = (size_t)(b * Kk + i0 + ii) * Dd + tid;
        __nv_bfloat16 h, l; split_bf16(cc[ii], h, l);
        ggh[idx] = h; ggl[idx] = l;
    }
}

// ---------------- layernorm over D=256 -> duals only ----------------
__device__ __forceinline__ float blocksum256(float v, float* red) {
    int lane = threadIdx.x & 31, w = threadIdx.x >> 5;
    #pragma unroll
    for (int o = 16; o; o >>= 1) v += __shfl_xor_sync(0xffffffffu, v, o);
    __syncthreads();
    if (lane == 0) red[w] = v;
    __syncthreads();
    float t = red[0];
    #pragma unroll
    for (int i = 1; i < 8; i++) t += red[i];
    return t;
}

__global__ void __launch_bounds__(256)
ln_kernel(const float* __restrict__ in, const float* __restrict__ gam,
          const float* __restrict__ bet,
          __nv_bfloat16* __restrict__ outh, __nv_bfloat16* __restrict__ outl)
{
    __shared__ float red[8];
    int r = blockIdx.x, tid = threadIdx.x;
    float v = in[r * Dd + tid];
    float mean = blocksum256(v, red) * (1.f / Dd);
    float dv = v - mean;
    float var = blocksum256(dv * dv, red) * (1.f / Dd);
    float o = dv * rsqrtf(var + 1e-5f) * gam[tid] + bet[tid];
    __nv_bfloat16 h, l; split_bf16(o, h, l);
    outh[r * Dd + tid] = h;
    outl[r * Dd + tid] = l;
}

// ---------------- pool + heads ----------------
__global__ void __launch_bounds__(256)
pool_kernel(const float* __restrict__ x, float* __restrict__ s)
{
    int b = blockIdx.x, d = threadIdx.x;
    float acc = 0.f;
    #pragma unroll 8
    for (int i = 0; i < Kk; i++) acc += x[(b * Kk + i) * Dd + d];
    s[b * Dd + d] = acc;
}

__global__ void __launch_bounds__(LSs)
head_kernel(const float* __restrict__ s,
            const float* __restrict__ pw, const float* __restrict__ pb,
            const float* __restrict__ muw, const float* __restrict__ mub,
            const float* __restrict__ spw, const float* __restrict__ spb,
            float* __restrict__ out)
{
    int b = blockIdx.x, n = threadIdx.x;
    __shared__ float ss[Dd];
    __shared__ float sh[LSs];
    ss[n]       = s[b * Dd + n];
    ss[n + 128] = s[b * Dd + n + 128];
    __syncthreads();

    float acc = pb[n];
    #pragma unroll 8
    for (int d = 0; d < Dd; d++) acc = fmaf(ss[d], pw[n * Dd + d], acc);
    sh[n] = 0.5f * acc * (1.0f + erff(acc * 0.7071067811865476f));
    __syncthreads();

    float mu = mub[n], sc = spb[n];
    #pragma unroll 8
    for (int d = 0; d < LSs; d++) {
        mu = fmaf(sh[d], muw[n * LSs + d], mu);
        sc = fmaf(sh[d], spw[n * LSs + d], sc);
    }
    float spv = fmaxf(sc, 0.f) + log1pf(expf(-fabsf(sc)));
    out[b * LSs + n] = mu;
    out[Bb * LSs + b * LSs + n] = spv;
}

// ---------------- launch ----------------
extern "C" void kernel_launch(void* const* d_in, const int* in_sizes, int n_in,
                              void* d_out, int out_size)
{
    (void)in_sizes; (void)n_in; (void)out_size;
    const float* X    = (const float*)d_in[0];
    const float* k_w  = (const float*)d_in[1];
    const float* q_w  = (const float*)d_in[2];
    const float* rw1  = (const float*)d_in[3];
    const float* rb1  = (const float*)d_in[4];
    const float* rw2  = (const float*)d_in[5];
    const float* rb2  = (const float*)d_in[6];
    const float* lng  = (const float*)d_in[7];
    const float* lnb  = (const float*)d_in[8];
    const float* mw1  = (const float*)d_in[9];
    const float* mb1  = (const float*)d_in[10];
    const float* mw2  = (const float*)d_in[11];
    const float* mb2  = (const float*)d_in[12];
    const float* pw   = (const float*)d_in[13];
    const float* pb   = (const float*)d_in[14];
    const float* muw  = (const float*)d_in[15];
    const float* mub  = (const float*)d_in[16];
    const float* spw  = (const float*)d_in[17];
    const float* spb  = (const float*)d_in[18];
    float* out = (float*)d_out;

    static float *px=nullptr,*pqkab=nullptr,*php=nullptr,*pbc=nullptr,*ps=nullptr;
    static __nv_bfloat16 *pxh,*pxl,*pggh,*pggl,*phh,*phl,*pth,*ptl,*pwch,*pwcl,*pw2h,*pw2l;
    if (!px) {
        cudaGetSymbolAddress((void**)&px,    g_x);
        cudaGetSymbolAddress((void**)&pqkab, g_qkab);
        cudaGetSymbolAddress((void**)&php,   g_hp);
        cudaGetSymbolAddress((void**)&pbc,   g_bc);
        cudaGetSymbolAddress((void**)&ps,    g_s);
        cudaGetSymbolAddress((void**)&pxh,   g_xh);
        cudaGetSymbolAddress((void**)&pxl,   g_xl);
        cudaGetSymbolAddress((void**)&pggh,  g_ggh);
        cudaGetSymbolAddress((void**)&pggl,  g_ggl);
        cudaGetSymbolAddress((void**)&phh,   g_hh);
        cudaGetSymbolAddress((void**)&phl,   g_hl);
        cudaGetSymbolAddress((void**)&pth,   g_th);
        cudaGetSymbolAddress((void**)&ptl,   g_tl);
        cudaGetSymbolAddress((void**)&pwch,  g_wch);
        cudaGetSymbolAddress((void**)&pwcl,  g_wcl);
        cudaGetSymbolAddress((void**)&pw2h,  g_w2h);
        cudaGetSymbolAddress((void**)&pw2l,  g_w2l);
        cudaFuncSetAttribute(tc_gemm, cudaFuncAttributeMaxDynamicSharedMemorySize, SM_TOT);
    }

    copy_conv_kernel<<<(Mm * Dd) / 256, 256>>>(X, px, pxh, pxl, Mm * Dd);

    for (int l = 0; l < NLl; l++) {
        const float* rw1_l = rw1 + l * Dd * 2 * Dd;
        const float* rb1_l = rb1 + l * Dd;
        const float* rw2_l = rw2 + l * Dd * Dd;
        const float* rb2_l = rb2 + l * Dd;
        const float* lg_l  = lng + l * Dd;
        const float* lb_l  = lnb + l * Dd;
        const float* mw1_l = mw1 + l * Dd * Dd;
        const float* mb1_l = mb1 + l * Dd;
        const float* mw2_l = mw2 + l * Dd * Dd;
        const float* mb2_l = mb2 + l * Dd;

        pack_kernel<<<(4 * Dd * Dd) / 256, 256>>>(k_w + l * Dd * Dd, q_w + l * Dd * Dd,
                                                  rw1_l, rb1_l, pwch, pwcl, pbc);
        w2pack_kernel<<<(3 * Dd * Dd) / 256, 256>>>(rw2_l, mw1_l, mw2_l, pw2h, pw2l);

        // fused k|q|a|bb projection: [2048,256] @ [1024,256]^T -> qkab fp32
        tc_gemm<<<dim3(16, 16), 256, SM_TOT>>>(pxh, pxl, pwch, pwcl, pbc, nullptr,
                                               pqkab, QS, nullptr, nullptr, 0);

        attn_kernel<<<dim3(Kk / 4, Bb), 256>>>(pqkab, pggh, pggl);

        // agg proj + residual -> php (fp32)
        tc_gemm<<<dim3(4, 16), 256, SM_TOT>>>(pggh, pggl, pw2h, pw2l, rb2_l, px,
                                              php, Dd, nullptr, nullptr, 0);
        ln_kernel<<<Mm, 256>>>(php, lg_l, lb_l, phh, phl);
        // mlp1 (gelu) -> t duals only
        tc_gemm<<<dim3(4, 16), 256, SM_TOT>>>(phh, phl, pw2h + Dd * Dd, pw2l + Dd * Dd,
                                              mb1_l, nullptr, nullptr, Dd, pth, ptl, 1);
        // mlp2 + residual -> px fp32 + duals
        tc_gemm<<<dim3(4, 16), 256, SM_TOT>>>(pth, ptl, pw2h + 2 * Dd * Dd, pw2l + 2 * Dd * Dd,
                                              mb2_l, px, px, Dd, pxh, pxl, 0);
    }

    pool_kernel<<<Bb, 256>>>(px, ps);
    head_kernel<<<Bb, LSs>>>(ps, pw, pb, muw, mub, spw, spb, out);
}